// round 12
// baseline (speedup 1.0000x reference)
#include <cuda_runtime.h>
#include <math.h>

#define BATCH 1024
#define CH 32
#define LIN 1024
#define LCONV 1041
#define LH 520

// ---------------- scratch (device globals; no allocation) ----------------
__device__ float g_filt[CH * 16];
__device__ float g_xpart[BATCH * 17];     // per-row partial: lags 0..15, row-sum at 16
__device__ float g_bn1_sc3[CH];
__device__ float g_bn1_sh[CH];
__device__ float g_x1pre[BATCH * CH * 31];
__device__ float g_x2pre[BATCH * CH * 31];
// channel-major partials: [c * BATCH + b] for coalesced reduction in k_bn23
__device__ float g_p2s[CH * BATCH];
__device__ float g_p2q[CH * BATCH];
__device__ float g_p3s[CH * BATCH];
__device__ float g_p3q[CH * BATCH];
__device__ float g_bn2_sc[CH], g_bn2_sh[CH], g_bn3_sc[CH], g_bn3_sh[CH];
__device__ float g_z[BATCH * 768];
__device__ float g_a1[BATCH * 1024];
__device__ float g_a2[BATCH * 512];
__device__ float g_a3[BATCH * 128];

// ---------------- x row statistics (+ filter bank computed by block 0) ----------------
__global__ __launch_bounds__(256) void k_xstats(const float* __restrict__ x,
                                                const float* __restrict__ la_a,
                                                const float* __restrict__ la_b) {
    __shared__ float xs[LIN + 16];
    __shared__ float part[8][17];
    int b = blockIdx.x, tid = threadIdx.x;
    int warp = tid >> 5, lane = tid & 31;

    if (b == 0) {  // filter bank: all consumers run in later kernels
        for (int idx = tid; idx < CH * 16; idx += 256) {
            int c = idx >> 4, k = idx & 15;
            const double A = 0.08, ep = 0.03, tal = 0.1;
            const double w = 6.283185307179586 * 50.0;
            const double coef = -ep / sqrt(1.0 - ep * ep);
            double ratio = (double)la_b[c] / (double)la_a[c];
            double t = (double)k / 15.0;
            double arg = w * (t - ratio - tal);
            g_filt[c * 16 + k] = (float)(A * exp(coef * arg) * (-sin(arg)));
        }
    }

    for (int i = tid; i < LIN; i += 256) xs[i] = x[b * LIN + i];
    if (tid < 16) xs[LIN + tid] = 0.f;
    __syncthreads();
    float acc[16];
#pragma unroll
    for (int d = 0; d < 16; d++) acc[d] = 0.f;
    float s = 0.f;
    for (int i = tid; i < LIN; i += 256) {
        float xi = xs[i];
        s += xi;
#pragma unroll
        for (int d = 0; d < 16; d++) acc[d] = fmaf(xi, xs[i + d], acc[d]);
    }
#pragma unroll
    for (int off = 16; off > 0; off >>= 1) {
        s += __shfl_down_sync(0xffffffffu, s, off);
#pragma unroll
        for (int d = 0; d < 16; d++)
            acc[d] += __shfl_down_sync(0xffffffffu, acc[d], off);
    }
    if (lane == 0) {
#pragma unroll
        for (int d = 0; d < 16; d++) part[warp][d] = acc[d];
        part[warp][16] = s;
    }
    __syncthreads();
    if (tid < 17) {
        float t = 0.f;
#pragma unroll
        for (int w = 0; w < 8; w++) t += part[w][tid];
        g_xpart[b * 17 + tid] = t;
    }
}

// ---------------- fused reduction + BN1 affine (single block, 544 threads) ----------------
__global__ __launch_bounds__(544) void k_redbn1(const float* __restrict__ la_bias,
                                                const float* __restrict__ g1,
                                                const float* __restrict__ b1) {
    __shared__ double Rs[17];
    int tid = threadIdx.x, warp = tid >> 5, lane = tid & 31;
    if (warp < 17) {
        double s = 0;
        for (int b = lane; b < BATCH; b += 32) s += (double)g_xpart[b * 17 + warp];
#pragma unroll
        for (int off = 16; off > 0; off >>= 1)
            s += __shfl_down_sync(0xffffffffu, s, off);
        if (lane == 0) Rs[warp] = s;
    }
    __syncthreads();
    if (tid < CH * 16) {
        int c = tid >> 4, k = tid & 15;
        double fk = (double)g_filt[c * 16 + k];
        double q = 0;
#pragma unroll
        for (int k2 = 0; k2 < 16; k2++) {
            int d = k2 - k; if (d < 0) d = -d;
            q += (double)g_filt[c * 16 + k2] * Rs[d];
        }
        q *= fk;
        double F1p = fk;
#pragma unroll
        for (int off = 8; off > 0; off >>= 1) {
            q += __shfl_down_sync(0xffffffffu, q, off, 16);
            F1p += __shfl_down_sync(0xffffffffu, F1p, off, 16);
        }
        if (k == 0) {
            double S = Rs[16];
            double N = (double)BATCH * (double)LCONV;
            double Ey = F1p * S / N;
            double var = q / N - Ey * Ey;
            double mean = (double)la_bias[c] + Ey;
            double inv = 1.0 / sqrt(var + 1e-5);
            double sc = (double)g1[c] * inv;
            g_bn1_sc3[c] = (float)(sc / 3.0);
            g_bn1_sh[c] = (float)((double)b1[c] - mean * sc);
        }
    }
}

// ---------------- pass 2: fused conv+BN+avgpool -> register-resident branches ----------------
#define HPAD 556
__global__ __launch_bounds__(256) void k_branch(
    const float* __restrict__ x, const float* __restrict__ la_bias,
    const float* __restrict__ a1_w, const float* __restrict__ a1_b,
    const float* __restrict__ e1_w, const float* __restrict__ e1_b,
    const float* __restrict__ f1_w, const float* __restrict__ f1_b,
    const float* __restrict__ fa_w, const float* __restrict__ fa_b) {
    __shared__ __align__(16) float xsg[130 * 28];
    __shared__ float hw[8][HPAD];
    int b = blockIdx.x, tid = threadIdx.x;
    int warp = tid >> 5, lane = tid & 31;
    const float* xr = x + b * LIN;

    for (int idx = tid; idx < 130 * 24; idx += 256) {
        int g = idx / 24, j = idx - g * 24;
        int pos = 8 * g + j;
        xsg[g * 28 + j] = (pos >= 16 && pos < 16 + LIN) ? xr[pos - 16] : 0.f;
    }
    __syncthreads();

    float* h = hw[warp];

    for (int cg = 0; cg < 4; cg++) {
        int c = warp + 8 * cg;
        float fw[16];
#pragma unroll
        for (int k = 0; k < 16; k++) fw[k] = g_filt[c * 16 + k];
        float cw[18];
#pragma unroll
        for (int j = 0; j < 18; j++) {
            float s = 0.f;
#pragma unroll
            for (int p = 0; p < 3; p++) {
                int k = j - p;
                if (k >= 0 && k < 16) s += fw[k];
            }
            cw[j] = s;
        }
        float sc3 = g_bn1_sc3[c];
        float sh2 = fmaf(3.f * la_bias[c], sc3, g_bn1_sh[c]);

        for (int g = lane; g < 130; g += 32) {
            const float4* p4 = (const float4*)&xsg[g * 28];
            float r[24];
#pragma unroll
            for (int w = 0; w < 6; w++) {
                float4 q = p4[w];
                r[4 * w] = q.x; r[4 * w + 1] = q.y; r[4 * w + 2] = q.z; r[4 * w + 3] = q.w;
            }
            int base = 4 * g + (g >> 2);
#pragma unroll
            for (int d = 0; d < 4; d++) {
                float s = 0.f;
#pragma unroll
                for (int j = 0; j < 18; j++) s = fmaf(r[2 * d + j], cw[j], s);
                h[base + d] = fmaf(s, sc3, sh2);
            }
        }
        __syncwarp();

        float mvA = 0.f, mvB = 0.f;
        if (lane < 31) {
            int hb = 17 * lane;
            float hr[34];
#pragma unroll
            for (int j = 0; j < 34; j++) hr[j] = h[hb + j + (j >> 4)];

            {
                float w8[8];
#pragma unroll
                for (int k = 0; k < 8; k++) w8[k] = a1_w[c * 8 + k];
                float wsum = 0.f;
#pragma unroll
                for (int k = 0; k < 8; k++) wsum += w8[k];
                float wbA = a1_b[c] - wsum;
                float ua[14];
#pragma unroll
                for (int i = 0; i < 14; i++) {
                    float a = wbA;
#pragma unroll
                    for (int k = 0; k < 8; k++) a = fmaf(hr[2 * i + k], w8[k], a);
                    ua[i] = fmaxf(a, 0.f);
                }
                float wE[8];
#pragma unroll
                for (int k = 0; k < 8; k++) wE[k] = e1_w[c * 8 + k];
                float wbE = 1.f - e1_b[c];
#pragma unroll
                for (int j = 0; j < 4; j++) {
                    float a = wbE;
#pragma unroll
                    for (int k = 0; k < 8; k++) a = fmaf(ua[2 * j + k], wE[k], a);
                    mvA = fmaxf(mvA, a);
                }
                g_x1pre[(b * CH + c) * 31 + lane] = mvA;
            }
            {
                float w8[8];
#pragma unroll
                for (int k = 0; k < 8; k++) w8[k] = f1_w[c * 8 + k];
                float wbF = 1.f - f1_b[c];
                float ub[14];
#pragma unroll
                for (int i = 0; i < 14; i++) {
                    float a = wbF;
#pragma unroll
                    for (int k = 0; k < 8; k++) a = fmaf(hr[2 * i + k], w8[k], a);
                    ub[i] = fmaxf(a, 0.f);
                }
                float wA[8];
#pragma unroll
                for (int k = 0; k < 8; k++) wA[k] = fa_w[c * 8 + k];
                float wsum = 0.f;
#pragma unroll
                for (int k = 0; k < 8; k++) wsum += wA[k];
                float wbA2 = fa_b[c] - wsum;
#pragma unroll
                for (int j = 0; j < 4; j++) {
                    float a = wbA2;
#pragma unroll
                    for (int k = 0; k < 8; k++) a = fmaf(ub[2 * j + k], wA[k], a);
                    mvB = fmaxf(mvB, a);
                }
                g_x2pre[(b * CH + c) * 31 + lane] = mvB;
            }
        }
        float sA = mvA, qA = mvA * mvA, sB = mvB, qB = mvB * mvB;
#pragma unroll
        for (int off = 16; off > 0; off >>= 1) {
            sA += __shfl_down_sync(0xffffffffu, sA, off);
            qA += __shfl_down_sync(0xffffffffu, qA, off);
            sB += __shfl_down_sync(0xffffffffu, sB, off);
            qB += __shfl_down_sync(0xffffffffu, qB, off);
        }
        if (lane == 0) {  // channel-major for coalesced k_bn23
            g_p2s[c * BATCH + b] = sA; g_p2q[c * BATCH + b] = qA;
            g_p3s[c * BATCH + b] = sB; g_p3q[c * BATCH + b] = qB;
        }
        __syncwarp();
    }
}

// ---------------- finalize BN2 / BN3 affine (coalesced, warp-shuffle reduce) ----------------
__global__ __launch_bounds__(256) void k_bn23(const float* __restrict__ g2,
                                              const float* __restrict__ b2,
                                              const float* __restrict__ g3,
                                              const float* __restrict__ b3) {
    int c = blockIdx.x, which = blockIdx.y, tid = threadIdx.x;
    int warp = tid >> 5, lane = tid & 31;
    const float* ps = (which ? g_p3s : g_p2s) + c * BATCH;
    const float* pq = (which ? g_p3q : g_p2q) + c * BATCH;
    double s = 0, q = 0;
    for (int b = tid; b < BATCH; b += 256) {
        s += (double)ps[b];
        q += (double)pq[b];
    }
#pragma unroll
    for (int off = 16; off > 0; off >>= 1) {
        s += __shfl_down_sync(0xffffffffu, s, off);
        q += __shfl_down_sync(0xffffffffu, q, off);
    }
    __shared__ double ss[8], sq[8];
    if (lane == 0) { ss[warp] = s; sq[warp] = q; }
    __syncthreads();
    if (tid == 0) {
        double S = 0, Q = 0;
#pragma unroll
        for (int w = 0; w < 8; w++) { S += ss[w]; Q += sq[w]; }
        double N = (double)BATCH * 31.0;
        double mean = S / N;
        double var = Q / N - mean * mean;
        double inv = 1.0 / sqrt(var + 1e-5);
        double gg = which ? (double)g3[c] : (double)g2[c];
        double bb = which ? (double)b3[c] : (double)b2[c];
        double sc = gg * inv;
        if (which) { g_bn3_sc[c] = (float)sc; g_bn3_sh[c] = (float)(bb - mean * sc); }
        else       { g_bn2_sc[c] = (float)sc; g_bn2_sh[c] = (float)(bb - mean * sc); }
    }
}

// ---------------- BN + final eventually conv -> concat features z (B,768) ----------------
__global__ __launch_bounds__(128) void k_final(const float* __restrict__ e2_w,
                                               const float* __restrict__ e2_b,
                                               const float* __restrict__ f2_w,
                                               const float* __restrict__ f2_b) {
    int b = blockIdx.x;
    for (int idx = threadIdx.x; idx < 768; idx += 128) {
        int ct = idx / 12, j = idx % 12;
        int c = ct & 31;
        bool second = ct >= 32;
        const float* pre = (second ? g_x2pre : g_x1pre) + (b * CH + c) * 31 + 2 * j;
        const float* w = (second ? f2_w : e2_w) + c * 8;
        float base = 1.f - (second ? f2_b[c] : e2_b[c]);
        float sc = second ? g_bn3_sc[c] : g_bn2_sc[c];
        float shv = second ? g_bn3_sh[c] : g_bn2_sh[c];
        float sw = 0.f, dot = 0.f;
#pragma unroll
        for (int k = 0; k < 8; k++) { sw += w[k]; dot = fmaf(pre[k], w[k], dot); }
        float val = base + shv * sw + sc * dot;
        g_z[b * 768 + idx] = fmaxf(val, 0.f);
    }
}

// ---------------- SGEMM 128 threads, BM=BN=64, BK=16, double-buffered (1 sync/iter) ----------------
__global__ __launch_bounds__(128) void sgemm128(const float* __restrict__ A,
                                                const float* __restrict__ B,
                                                const float* __restrict__ bias,
                                                float* __restrict__ C,
                                                int M, int N, int K) {
    constexpr int BM = 64, BN = 64, BK = 16;
    const int tid = threadIdx.x;
    const int tx = tid & 7;
    const int ty = tid >> 3;
    const int m0 = blockIdx.y * BM;
    const int n0 = blockIdx.x * BN;
    __shared__ __align__(16) float As[2][BK][BM + 4];
    __shared__ __align__(16) float Bs[2][BK][BN + 4];
    float acc[4][8];
#pragma unroll
    for (int i = 0; i < 4; i++)
#pragma unroll
        for (int j = 0; j < 8; j++) acc[i][j] = 0.f;

    float4 pa[2], pb[2];
    const int nt = K / BK;

    auto loadG = [&](int t) {
        int k0 = t * BK;
#pragma unroll
        for (int L = 0; L < 2; L++) {
            int i = tid + L * 128;
            int ar = i >> 2, ac = i & 3;
            pa[L] = *(const float4*)(A + (size_t)(m0 + ar) * K + k0 + ac * 4);
            int br = i >> 4, bc = i & 15;
            pb[L] = *(const float4*)(B + (size_t)(k0 + br) * N + n0 + bc * 4);
        }
    };
    auto storeS = [&](int st) {
#pragma unroll
        for (int L = 0; L < 2; L++) {
            int i = tid + L * 128;
            int ar = i >> 2, ac = i & 3;
            As[st][ac * 4 + 0][ar] = pa[L].x; As[st][ac * 4 + 1][ar] = pa[L].y;
            As[st][ac * 4 + 2][ar] = pa[L].z; As[st][ac * 4 + 3][ar] = pa[L].w;
            int br = i >> 4, bc = i & 15;
            *(float4*)(&Bs[st][br][bc * 4]) = pb[L];
        }
    };

    loadG(0); storeS(0); __syncthreads();
    int cur = 0;
    for (int t = 0; t < nt; t++) {
        if (t + 1 < nt) loadG(t + 1);
#pragma unroll
        for (int kk = 0; kk < BK; kk++) {
            float4 qa = *(const float4*)(&As[cur][kk][ty * 4]);
            float af[4] = {qa.x, qa.y, qa.z, qa.w};
            float bf[8];
#pragma unroll
            for (int j = 0; j < 8; j += 4) {
                float4 qb = *(const float4*)(&Bs[cur][kk][tx * 8 + j]);
                bf[j] = qb.x; bf[j + 1] = qb.y; bf[j + 2] = qb.z; bf[j + 3] = qb.w;
            }
#pragma unroll
            for (int i = 0; i < 4; i++)
#pragma unroll
                for (int j = 0; j < 8; j++) acc[i][j] = fmaf(af[i], bf[j], acc[i][j]);
        }
        if (t + 1 < nt) storeS(cur ^ 1);
        __syncthreads();
        cur ^= 1;
    }
#pragma unroll
    for (int i = 0; i < 4; i++) {
        int m = m0 + ty * 4 + i;
#pragma unroll
        for (int j = 0; j < 8; j += 4) {
            int n = n0 + tx * 8 + j;
            float4 o;
            o.x = fmaxf(acc[i][j] + bias[n], 0.f);
            o.y = fmaxf(acc[i][j + 1] + bias[n + 1], 0.f);
            o.z = fmaxf(acc[i][j + 2] + bias[n + 2], 0.f);
            o.w = fmaxf(acc[i][j + 3] + bias[n + 3], 0.f);
            *(float4*)(C + (size_t)m * N + n) = o;
        }
    }
}

// ---------------- SGEMM small-N (32x32, 64 threads) for GEMM3 (proven) ----------------
template <int BM, int TM>
__global__ __launch_bounds__(64) void sgemm_relu(const float* __restrict__ A,
                                                 const float* __restrict__ B,
                                                 const float* __restrict__ bias,
                                                 float* __restrict__ C,
                                                 int M, int N, int K) {
    constexpr int BK = 8;
    constexpr int LPT = (BM * BK / 4) / 64;
    const int tid = threadIdx.x;
    const int tx = tid & 7;
    const int ty = tid >> 3;
    const int m0 = blockIdx.y * BM;
    const int n0 = blockIdx.x * BM;
    __shared__ float As[BK][BM];
    __shared__ float Bs[BK][BM];
    float acc[TM][TM];
#pragma unroll
    for (int i = 0; i < TM; i++)
#pragma unroll
        for (int j = 0; j < TM; j++) acc[i][j] = 0.f;

    float4 pa[LPT], pb[LPT];
    const int nt = K / BK;

    auto loadG = [&](int t) {
        int k0 = t * BK;
#pragma unroll
        for (int L = 0; L < LPT; L++) {
            int i = tid + L * 64;
            int ar = i >> 1, ag = i & 1;
            pa[L] = *(const float4*)(A + (size_t)(m0 + ar) * K + k0 + ag * 4);
            int bk = i / (BM / 4), bc = i % (BM / 4);
            pb[L] = *(const float4*)(B + (size_t)(k0 + bk) * N + n0 + bc * 4);
        }
    };
    auto storeS = [&]() {
#pragma unroll
        for (int L = 0; L < LPT; L++) {
            int i = tid + L * 64;
            int ar = i >> 1, ag = i & 1;
            As[ag * 4 + 0][ar] = pa[L].x; As[ag * 4 + 1][ar] = pa[L].y;
            As[ag * 4 + 2][ar] = pa[L].z; As[ag * 4 + 3][ar] = pa[L].w;
            int bk = i / (BM / 4), bc = i % (BM / 4);
            *(float4*)(&Bs[bk][bc * 4]) = pb[L];
        }
    };

    loadG(0); storeS(); __syncthreads();
    for (int t = 0; t < nt; t++) {
        if (t + 1 < nt) loadG(t + 1);
#pragma unroll
        for (int kk = 0; kk < BK; kk++) {
            float af[TM], bf[TM];
#pragma unroll
            for (int i = 0; i < TM; i += 4) {
                float4 qa = *(const float4*)(&As[kk][ty * TM + i]);
                af[i] = qa.x; af[i + 1] = qa.y; af[i + 2] = qa.z; af[i + 3] = qa.w;
            }
#pragma unroll
            for (int j = 0; j < TM; j += 4) {
                float4 qb = *(const float4*)(&Bs[kk][tx * TM + j]);
                bf[j] = qb.x; bf[j + 1] = qb.y; bf[j + 2] = qb.z; bf[j + 3] = qb.w;
            }
#pragma unroll
            for (int i = 0; i < TM; i++)
#pragma unroll
                for (int j = 0; j < TM; j++) acc[i][j] = fmaf(af[i], bf[j], acc[i][j]);
        }
        __syncthreads();
        if (t + 1 < nt) { storeS(); __syncthreads(); }
    }
#pragma unroll
    for (int i = 0; i < TM; i++) {
        int m = m0 + ty * TM + i;
#pragma unroll
        for (int j = 0; j < TM; j += 4) {
            int n = n0 + tx * TM + j;
            float4 o;
            o.x = fmaxf(acc[i][j] + bias[n], 0.f);
            o.y = fmaxf(acc[i][j + 1] + bias[n + 1], 0.f);
            o.z = fmaxf(acc[i][j + 2] + bias[n + 2], 0.f);
            o.w = fmaxf(acc[i][j + 3] + bias[n + 3], 0.f);
            *(float4*)(C + (size_t)m * N + n) = o;
        }
    }
}

// ---------------- last tiny FC: (1024,128)@(128,10)+b, relu ----------------
__global__ void k_fc4(const float* __restrict__ w4, const float* __restrict__ b4,
                      float* __restrict__ out) {
    int idx = blockIdx.x * blockDim.x + threadIdx.x;
    if (idx >= BATCH * 10) return;
    int b = idx / 10, n = idx - b * 10;
    const float* a = g_a3 + b * 128;
    float acc = b4[n];
#pragma unroll 8
    for (int k = 0; k < 128; k++) acc = fmaf(a[k], w4[k * 10 + n], acc);
    out[idx] = fmaxf(acc, 0.f);
}

// ---------------- launch ----------------
extern "C" void kernel_launch(void* const* d_in, const int* in_sizes, int n_in,
                              void* d_out, int out_size) {
    const float* x       = (const float*)d_in[0];
    const float* la_a    = (const float*)d_in[1];
    const float* la_b    = (const float*)d_in[2];
    const float* la_bias = (const float*)d_in[3];
    const float* bn1_g   = (const float*)d_in[4];
    const float* bn1_b   = (const float*)d_in[5];
    const float* a1_w    = (const float*)d_in[6];
    const float* a1_b    = (const float*)d_in[7];
    const float* e1_w    = (const float*)d_in[8];
    const float* e1_b    = (const float*)d_in[9];
    const float* bn2_g   = (const float*)d_in[10];
    const float* bn2_b   = (const float*)d_in[11];
    const float* e2_w    = (const float*)d_in[12];
    const float* e2_b    = (const float*)d_in[13];
    const float* f1_w    = (const float*)d_in[14];
    const float* f1_b    = (const float*)d_in[15];
    const float* fa_w    = (const float*)d_in[16];
    const float* fa_b    = (const float*)d_in[17];
    const float* bn3_g   = (const float*)d_in[18];
    const float* bn3_b   = (const float*)d_in[19];
    const float* f2_w    = (const float*)d_in[20];
    const float* f2_b    = (const float*)d_in[21];
    const float* w1 = (const float*)d_in[22]; const float* b1 = (const float*)d_in[23];
    const float* w2 = (const float*)d_in[24]; const float* b2 = (const float*)d_in[25];
    const float* w3 = (const float*)d_in[26]; const float* b3 = (const float*)d_in[27];
    const float* w4 = (const float*)d_in[28]; const float* b4 = (const float*)d_in[29];
    float* out = (float*)d_out;

    float *p_z = nullptr, *p_a1 = nullptr, *p_a2 = nullptr, *p_a3 = nullptr;
    cudaGetSymbolAddress((void**)&p_z, g_z);
    cudaGetSymbolAddress((void**)&p_a1, g_a1);
    cudaGetSymbolAddress((void**)&p_a2, g_a2);
    cudaGetSymbolAddress((void**)&p_a3, g_a3);

    k_xstats<<<BATCH, 256>>>(x, la_a, la_b);
    k_redbn1<<<1, 544>>>(la_bias, bn1_g, bn1_b);
    k_branch<<<BATCH, 256>>>(x, la_bias, a1_w, a1_b, e1_w, e1_b,
                             f1_w, f1_b, fa_w, fa_b);
    k_bn23<<<dim3(CH, 2), 256>>>(bn2_g, bn2_b, bn3_g, bn3_b);
    k_final<<<BATCH, 128>>>(e2_w, e2_b, f2_w, f2_b);
    sgemm128<<<dim3(1024 / 64, 1024 / 64), 128>>>(p_z, w1, b1, p_a1, 1024, 1024, 768);
    sgemm128<<<dim3(512 / 64, 1024 / 64), 128>>>(p_a1, w2, b2, p_a2, 1024, 512, 1024);
    sgemm_relu<32, 4><<<dim3(128 / 32, 1024 / 32), 64>>>(p_a2, w3, b3, p_a3, 1024, 128, 512);
    k_fc4<<<(BATCH * 10 + 127) / 128, 128>>>(w4, b4, out);
}

// round 14
// speedup vs baseline: 1.2715x; 1.2715x over previous
#include <cuda_runtime.h>
#include <cuda_bf16.h>
#include <math.h>

#define BATCH 1024
#define CH 32
#define LIN 1024
#define LCONV 1041
#define LH 520

typedef unsigned int u32;

// ---------------- scratch (device globals; no allocation) ----------------
__device__ float g_filt[CH * 16];
__device__ float g_xpart[BATCH * 17];
__device__ float g_bn1_sc3[CH];
__device__ float g_bn1_sh[CH];
__device__ float g_x1pre[BATCH * CH * 31];
__device__ float g_x2pre[BATCH * CH * 31];
__device__ float g_p2s[CH * BATCH];
__device__ float g_p2q[CH * BATCH];
__device__ float g_p3s[CH * BATCH];
__device__ float g_p3q[CH * BATCH];
__device__ float g_bn2_sc[CH], g_bn2_sh[CH], g_bn3_sc[CH], g_bn3_sh[CH];
// split-bf16 buffers
__device__ __align__(16) __nv_bfloat16 g_zhi[BATCH * 768];
__device__ __align__(16) __nv_bfloat16 g_zlo[BATCH * 768];
__device__ __align__(16) __nv_bfloat16 g_w1hi[1024 * 768];   // [N][K] transposed
__device__ __align__(16) __nv_bfloat16 g_w1lo[1024 * 768];
__device__ __align__(16) __nv_bfloat16 g_a1hi[BATCH * 1024];
__device__ __align__(16) __nv_bfloat16 g_a1lo[BATCH * 1024];
__device__ __align__(16) __nv_bfloat16 g_w2hi[512 * 1024];   // [N][K] transposed
__device__ __align__(16) __nv_bfloat16 g_w2lo[512 * 1024];
__device__ float g_a2[BATCH * 512];
__device__ float g_a3[BATCH * 128];

// ---------------- x row statistics (+ filter bank computed by block 0) ----------------
__global__ __launch_bounds__(256) void k_xstats(const float* __restrict__ x,
                                                const float* __restrict__ la_a,
                                                const float* __restrict__ la_b) {
    __shared__ float xs[LIN + 16];
    __shared__ float part[8][17];
    int b = blockIdx.x, tid = threadIdx.x;
    int warp = tid >> 5, lane = tid & 31;

    if (b == 0) {
        for (int idx = tid; idx < CH * 16; idx += 256) {
            int c = idx >> 4, k = idx & 15;
            const double A = 0.08, ep = 0.03, tal = 0.1;
            const double w = 6.283185307179586 * 50.0;
            const double coef = -ep / sqrt(1.0 - ep * ep);
            double ratio = (double)la_b[c] / (double)la_a[c];
            double t = (double)k / 15.0;
            double arg = w * (t - ratio - tal);
            g_filt[c * 16 + k] = (float)(A * exp(coef * arg) * (-sin(arg)));
        }
    }

    for (int i = tid; i < LIN; i += 256) xs[i] = x[b * LIN + i];
    if (tid < 16) xs[LIN + tid] = 0.f;
    __syncthreads();
    float acc[16];
#pragma unroll
    for (int d = 0; d < 16; d++) acc[d] = 0.f;
    float s = 0.f;
    for (int i = tid; i < LIN; i += 256) {
        float xi = xs[i];
        s += xi;
#pragma unroll
        for (int d = 0; d < 16; d++) acc[d] = fmaf(xi, xs[i + d], acc[d]);
    }
#pragma unroll
    for (int off = 16; off > 0; off >>= 1) {
        s += __shfl_down_sync(0xffffffffu, s, off);
#pragma unroll
        for (int d = 0; d < 16; d++)
            acc[d] += __shfl_down_sync(0xffffffffu, acc[d], off);
    }
    if (lane == 0) {
#pragma unroll
        for (int d = 0; d < 16; d++) part[warp][d] = acc[d];
        part[warp][16] = s;
    }
    __syncthreads();
    if (tid < 17) {
        float t = 0.f;
#pragma unroll
        for (int w = 0; w < 8; w++) t += part[w][tid];
        g_xpart[b * 17 + tid] = t;
    }
}

// ---------------- fused reduction + BN1 affine ----------------
__global__ __launch_bounds__(544) void k_redbn1(const float* __restrict__ la_bias,
                                                const float* __restrict__ g1,
                                                const float* __restrict__ b1) {
    __shared__ double Rs[17];
    int tid = threadIdx.x, warp = tid >> 5, lane = tid & 31;
    if (warp < 17) {
        double s = 0;
        for (int b = lane; b < BATCH; b += 32) s += (double)g_xpart[b * 17 + warp];
#pragma unroll
        for (int off = 16; off > 0; off >>= 1)
            s += __shfl_down_sync(0xffffffffu, s, off);
        if (lane == 0) Rs[warp] = s;
    }
    __syncthreads();
    if (tid < CH * 16) {
        int c = tid >> 4, k = tid & 15;
        double fk = (double)g_filt[c * 16 + k];
        double q = 0;
#pragma unroll
        for (int k2 = 0; k2 < 16; k2++) {
            int d = k2 - k; if (d < 0) d = -d;
            q += (double)g_filt[c * 16 + k2] * Rs[d];
        }
        q *= fk;
        double F1p = fk;
#pragma unroll
        for (int off = 8; off > 0; off >>= 1) {
            q += __shfl_down_sync(0xffffffffu, q, off, 16);
            F1p += __shfl_down_sync(0xffffffffu, F1p, off, 16);
        }
        if (k == 0) {
            double S = Rs[16];
            double N = (double)BATCH * (double)LCONV;
            double Ey = F1p * S / N;
            double var = q / N - Ey * Ey;
            double mean = (double)la_bias[c] + Ey;
            double inv = 1.0 / sqrt(var + 1e-5);
            double sc = (double)g1[c] * inv;
            g_bn1_sc3[c] = (float)(sc / 3.0);
            g_bn1_sh[c] = (float)((double)b1[c] - mean * sc);
        }
    }
}

// ---------------- pass 2: fused conv+BN+avgpool -> register-resident branches ----------------
#define HPAD 556
__global__ __launch_bounds__(256) void k_branch(
    const float* __restrict__ x, const float* __restrict__ la_bias,
    const float* __restrict__ a1_w, const float* __restrict__ a1_b,
    const float* __restrict__ e1_w, const float* __restrict__ e1_b,
    const float* __restrict__ f1_w, const float* __restrict__ f1_b,
    const float* __restrict__ fa_w, const float* __restrict__ fa_b) {
    __shared__ __align__(16) float xsg[130 * 28];
    __shared__ float hw[8][HPAD];
    int b = blockIdx.x, tid = threadIdx.x;
    int warp = tid >> 5, lane = tid & 31;
    const float* xr = x + b * LIN;

    for (int idx = tid; idx < 130 * 24; idx += 256) {
        int g = idx / 24, j = idx - g * 24;
        int pos = 8 * g + j;
        xsg[g * 28 + j] = (pos >= 16 && pos < 16 + LIN) ? xr[pos - 16] : 0.f;
    }
    __syncthreads();

    float* h = hw[warp];

    for (int cg = 0; cg < 4; cg++) {
        int c = warp + 8 * cg;
        float fw[16];
#pragma unroll
        for (int k = 0; k < 16; k++) fw[k] = g_filt[c * 16 + k];
        float cw[18];
#pragma unroll
        for (int j = 0; j < 18; j++) {
            float s = 0.f;
#pragma unroll
            for (int p = 0; p < 3; p++) {
                int k = j - p;
                if (k >= 0 && k < 16) s += fw[k];
            }
            cw[j] = s;
        }
        float sc3 = g_bn1_sc3[c];
        float sh2 = fmaf(3.f * la_bias[c], sc3, g_bn1_sh[c]);

        for (int g = lane; g < 130; g += 32) {
            const float4* p4 = (const float4*)&xsg[g * 28];
            float r[24];
#pragma unroll
            for (int w = 0; w < 6; w++) {
                float4 q = p4[w];
                r[4 * w] = q.x; r[4 * w + 1] = q.y; r[4 * w + 2] = q.z; r[4 * w + 3] = q.w;
            }
            int base = 4 * g + (g >> 2);
#pragma unroll
            for (int d = 0; d < 4; d++) {
                float s = 0.f;
#pragma unroll
                for (int j = 0; j < 18; j++) s = fmaf(r[2 * d + j], cw[j], s);
                h[base + d] = fmaf(s, sc3, sh2);
            }
        }
        __syncwarp();

        float mvA = 0.f, mvB = 0.f;
        if (lane < 31) {
            int hb = 17 * lane;
            float hr[34];
#pragma unroll
            for (int j = 0; j < 34; j++) hr[j] = h[hb + j + (j >> 4)];

            {
                float w8[8];
#pragma unroll
                for (int k = 0; k < 8; k++) w8[k] = a1_w[c * 8 + k];
                float wsum = 0.f;
#pragma unroll
                for (int k = 0; k < 8; k++) wsum += w8[k];
                float wbA = a1_b[c] - wsum;
                float ua[14];
#pragma unroll
                for (int i = 0; i < 14; i++) {
                    float a = wbA;
#pragma unroll
                    for (int k = 0; k < 8; k++) a = fmaf(hr[2 * i + k], w8[k], a);
                    ua[i] = fmaxf(a, 0.f);
                }
                float wE[8];
#pragma unroll
                for (int k = 0; k < 8; k++) wE[k] = e1_w[c * 8 + k];
                float wbE = 1.f - e1_b[c];
#pragma unroll
                for (int j = 0; j < 4; j++) {
                    float a = wbE;
#pragma unroll
                    for (int k = 0; k < 8; k++) a = fmaf(ua[2 * j + k], wE[k], a);
                    mvA = fmaxf(mvA, a);
                }
                g_x1pre[(b * CH + c) * 31 + lane] = mvA;
            }
            {
                float w8[8];
#pragma unroll
                for (int k = 0; k < 8; k++) w8[k] = f1_w[c * 8 + k];
                float wbF = 1.f - f1_b[c];
                float ub[14];
#pragma unroll
                for (int i = 0; i < 14; i++) {
                    float a = wbF;
#pragma unroll
                    for (int k = 0; k < 8; k++) a = fmaf(hr[2 * i + k], w8[k], a);
                    ub[i] = fmaxf(a, 0.f);
                }
                float wA[8];
#pragma unroll
                for (int k = 0; k < 8; k++) wA[k] = fa_w[c * 8 + k];
                float wsum = 0.f;
#pragma unroll
                for (int k = 0; k < 8; k++) wsum += wA[k];
                float wbA2 = fa_b[c] - wsum;
#pragma unroll
                for (int j = 0; j < 4; j++) {
                    float a = wbA2;
#pragma unroll
                    for (int k = 0; k < 8; k++) a = fmaf(ub[2 * j + k], wA[k], a);
                    mvB = fmaxf(mvB, a);
                }
                g_x2pre[(b * CH + c) * 31 + lane] = mvB;
            }
        }
        float sA = mvA, qA = mvA * mvA, sB = mvB, qB = mvB * mvB;
#pragma unroll
        for (int off = 16; off > 0; off >>= 1) {
            sA += __shfl_down_sync(0xffffffffu, sA, off);
            qA += __shfl_down_sync(0xffffffffu, qA, off);
            sB += __shfl_down_sync(0xffffffffu, sB, off);
            qB += __shfl_down_sync(0xffffffffu, qB, off);
        }
        if (lane == 0) {
            g_p2s[c * BATCH + b] = sA; g_p2q[c * BATCH + b] = qA;
            g_p3s[c * BATCH + b] = sB; g_p3q[c * BATCH + b] = qB;
        }
        __syncwarp();
    }
}

// ---------------- finalize BN2 / BN3 affine (coalesced) ----------------
__global__ __launch_bounds__(256) void k_bn23(const float* __restrict__ g2,
                                              const float* __restrict__ b2,
                                              const float* __restrict__ g3,
                                              const float* __restrict__ b3) {
    int c = blockIdx.x, which = blockIdx.y, tid = threadIdx.x;
    int warp = tid >> 5, lane = tid & 31;
    const float* ps = (which ? g_p3s : g_p2s) + c * BATCH;
    const float* pq = (which ? g_p3q : g_p2q) + c * BATCH;
    double s = 0, q = 0;
    for (int b = tid; b < BATCH; b += 256) {
        s += (double)ps[b];
        q += (double)pq[b];
    }
#pragma unroll
    for (int off = 16; off > 0; off >>= 1) {
        s += __shfl_down_sync(0xffffffffu, s, off);
        q += __shfl_down_sync(0xffffffffu, q, off);
    }
    __shared__ double ss[8], sq[8];
    if (lane == 0) { ss[warp] = s; sq[warp] = q; }
    __syncthreads();
    if (tid == 0) {
        double S = 0, Q = 0;
#pragma unroll
        for (int w = 0; w < 8; w++) { S += ss[w]; Q += sq[w]; }
        double N = (double)BATCH * 31.0;
        double mean = S / N;
        double var = Q / N - mean * mean;
        double inv = 1.0 / sqrt(var + 1e-5);
        double gg = which ? (double)g3[c] : (double)g2[c];
        double bb = which ? (double)b3[c] : (double)b2[c];
        double sc = gg * inv;
        if (which) { g_bn3_sc[c] = (float)sc; g_bn3_sh[c] = (float)(bb - mean * sc); }
        else       { g_bn2_sc[c] = (float)sc; g_bn2_sh[c] = (float)(bb - mean * sc); }
    }
}

// ---------------- BN + final conv -> z features emitted as split bf16 ----------------
__global__ __launch_bounds__(128) void k_final(const float* __restrict__ e2_w,
                                               const float* __restrict__ e2_b,
                                               const float* __restrict__ f2_w,
                                               const float* __restrict__ f2_b) {
    int b = blockIdx.x;
    for (int idx = threadIdx.x; idx < 768; idx += 128) {
        int ct = idx / 12, j = idx % 12;
        int c = ct & 31;
        bool second = ct >= 32;
        const float* pre = (second ? g_x2pre : g_x1pre) + (b * CH + c) * 31 + 2 * j;
        const float* w = (second ? f2_w : e2_w) + c * 8;
        float base = 1.f - (second ? f2_b[c] : e2_b[c]);
        float sc = second ? g_bn3_sc[c] : g_bn2_sc[c];
        float shv = second ? g_bn3_sh[c] : g_bn2_sh[c];
        float sw = 0.f, dot = 0.f;
#pragma unroll
        for (int k = 0; k < 8; k++) { sw += w[k]; dot = fmaf(pre[k], w[k], dot); }
        float val = fmaxf(base + shv * sw + sc * dot, 0.f);
        __nv_bfloat16 hi = __float2bfloat16(val);
        __nv_bfloat16 lo = __float2bfloat16(val - __bfloat162float(hi));
        g_zhi[b * 768 + idx] = hi;
        g_zlo[b * 768 + idx] = lo;
    }
}

// ---------------- weight transpose + split: w[K][N] fp32 -> wt_hi/lo[N][K] bf16 ----------------
__global__ __launch_bounds__(256) void k_wsplit(const float* __restrict__ w,
                                                __nv_bfloat16* __restrict__ whi,
                                                __nv_bfloat16* __restrict__ wlo,
                                                int K, int N) {
    __shared__ float ts[32][33];
    int n0 = blockIdx.x * 32, k0 = blockIdx.y * 32;
    int tx = threadIdx.x & 31, ty = threadIdx.x >> 5;
#pragma unroll
    for (int i = 0; i < 4; i++)
        ts[ty + i * 8][tx] = w[(size_t)(k0 + ty + i * 8) * N + n0 + tx];
    __syncthreads();
#pragma unroll
    for (int i = 0; i < 4; i++) {
        float v = ts[tx][ty + i * 8];
        __nv_bfloat16 hi = __float2bfloat16(v);
        __nv_bfloat16 lo = __float2bfloat16(v - __bfloat162float(hi));
        size_t o = (size_t)(n0 + ty + i * 8) * K + k0 + tx;
        whi[o] = hi; wlo[o] = lo;
    }
}

// ---------------- split-bf16 HMMA GEMM: C = relu(A@B^T + bias) ----------------
// A: [M][K] bf16 hi/lo row-major. B: [N][K] bf16 hi/lo (transposed weights).
// Block 128x64, 256 threads, 8 warps (4m x 2n), warp tile 32x32, BK=32.
__device__ __forceinline__ void mma_bf16(float* d, const u32* a, const u32* b) {
    asm volatile(
        "mma.sync.aligned.m16n8k16.row.col.f32.bf16.bf16.f32 "
        "{%0,%1,%2,%3}, {%4,%5,%6,%7}, {%8,%9}, {%0,%1,%2,%3};\n"
        : "+f"(d[0]), "+f"(d[1]), "+f"(d[2]), "+f"(d[3])
        : "r"(a[0]), "r"(a[1]), "r"(a[2]), "r"(a[3]), "r"(b[0]), "r"(b[1]));
}

template <int EMIT_SPLIT>
__global__ __launch_bounds__(256) void hgemm_split(
    const __nv_bfloat16* __restrict__ Ahi, const __nv_bfloat16* __restrict__ Alo,
    const __nv_bfloat16* __restrict__ Bhi, const __nv_bfloat16* __restrict__ Blo,
    const float* __restrict__ bias,
    float* __restrict__ Cf,
    __nv_bfloat16* __restrict__ Chi, __nv_bfloat16* __restrict__ Clo,
    int M, int N, int K) {
    constexpr int BM = 128, BN = 64, BK = 32;
    __shared__ u32 AsH[128 * 20], AsL[128 * 20], BsH[64 * 20], BsL[64 * 20];
    const int tid = threadIdx.x;
    const int warp = tid >> 5, lane = tid & 31;
    const int g = lane >> 2, tg = lane & 3;
    const int wm = (warp & 3) * 32, wn = (warp >> 2) * 32;
    const int m0 = blockIdx.y * BM, n0 = blockIdx.x * BN;

    float acc[2][4][4];
#pragma unroll
    for (int f = 0; f < 2; f++)
#pragma unroll
        for (int j = 0; j < 4; j++)
#pragma unroll
            for (int e = 0; e < 4; e++) acc[f][j][e] = 0.f;

    const int ra = tid >> 1, pa = tid & 1;   // A: 128 rows x 2 halves
    const int rb = tid >> 2, qb = tid & 3;   // B: 64 rows x 4 quarters
    const int nt = K / BK;

    for (int t = 0; t < nt; t++) {
        int k0 = t * BK;
        __syncthreads();
        {
            const uint4* gah = (const uint4*)(Ahi + (size_t)(m0 + ra) * K + k0);
            const uint4* gal = (const uint4*)(Alo + (size_t)(m0 + ra) * K + k0);
            uint4* sh = (uint4*)&AsH[ra * 20 + pa * 8];
            uint4* sl = (uint4*)&AsL[ra * 20 + pa * 8];
            sh[0] = gah[2 * pa]; sh[1] = gah[2 * pa + 1];
            sl[0] = gal[2 * pa]; sl[1] = gal[2 * pa + 1];
            ((uint4*)&BsH[rb * 20 + qb * 4])[0] =
                ((const uint4*)(Bhi + (size_t)(n0 + rb) * K + k0))[qb];
            ((uint4*)&BsL[rb * 20 + qb * 4])[0] =
                ((const uint4*)(Blo + (size_t)(n0 + rb) * K + k0))[qb];
        }
        __syncthreads();
#pragma unroll
        for (int ks = 0; ks < 2; ks++) {
            int ko = ks * 8;
            u32 ah[2][4], al[2][4];
#pragma unroll
            for (int f = 0; f < 2; f++) {
                int r0 = wm + f * 16 + g;
                ah[f][0] = AsH[r0 * 20 + ko + tg];
                ah[f][1] = AsH[(r0 + 8) * 20 + ko + tg];
                ah[f][2] = AsH[r0 * 20 + ko + tg + 4];
                ah[f][3] = AsH[(r0 + 8) * 20 + ko + tg + 4];
                al[f][0] = AsL[r0 * 20 + ko + tg];
                al[f][1] = AsL[(r0 + 8) * 20 + ko + tg];
                al[f][2] = AsL[r0 * 20 + ko + tg + 4];
                al[f][3] = AsL[(r0 + 8) * 20 + ko + tg + 4];
            }
            u32 bh[4][2], bl[4][2];
#pragma unroll
            for (int j = 0; j < 4; j++) {
                int rn = wn + j * 8 + g;
                bh[j][0] = BsH[rn * 20 + ko + tg];
                bh[j][1] = BsH[rn * 20 + ko + tg + 4];
                bl[j][0] = BsL[rn * 20 + ko + tg];
                bl[j][1] = BsL[rn * 20 + ko + tg + 4];
            }
#pragma unroll
            for (int f = 0; f < 2; f++)
#pragma unroll
                for (int j = 0; j < 4; j++) {
                    mma_bf16(acc[f][j], ah[f], bh[j]);
                    mma_bf16(acc[f][j], ah[f], bl[j]);
                    mma_bf16(acc[f][j], al[f], bh[j]);
                }
        }
    }
    // epilogue
#pragma unroll
    for (int f = 0; f < 2; f++) {
        int row = m0 + wm + f * 16 + g;
#pragma unroll
        for (int j = 0; j < 4; j++) {
            int col = n0 + wn + j * 8 + tg * 2;
            float bv0 = bias[col], bv1 = bias[col + 1];
            float v00 = fmaxf(acc[f][j][0] + bv0, 0.f);
            float v01 = fmaxf(acc[f][j][1] + bv1, 0.f);
            float v10 = fmaxf(acc[f][j][2] + bv0, 0.f);
            float v11 = fmaxf(acc[f][j][3] + bv1, 0.f);
            if (EMIT_SPLIT) {
                __nv_bfloat162 h0, l0, h1, l1;
                h0.x = __float2bfloat16(v00);
                h0.y = __float2bfloat16(v01);
                l0.x = __float2bfloat16(v00 - __bfloat162float(h0.x));
                l0.y = __float2bfloat16(v01 - __bfloat162float(h0.y));
                h1.x = __float2bfloat16(v10);
                h1.y = __float2bfloat16(v11);
                l1.x = __float2bfloat16(v10 - __bfloat162float(h1.x));
                l1.y = __float2bfloat16(v11 - __bfloat162float(h1.y));
                *(__nv_bfloat162*)(Chi + (size_t)row * N + col) = h0;
                *(__nv_bfloat162*)(Clo + (size_t)row * N + col) = l0;
                *(__nv_bfloat162*)(Chi + (size_t)(row + 8) * N + col) = h1;
                *(__nv_bfloat162*)(Clo + (size_t)(row + 8) * N + col) = l1;
            } else {
                *(float2*)(Cf + (size_t)row * N + col) = make_float2(v00, v01);
                *(float2*)(Cf + (size_t)(row + 8) * N + col) = make_float2(v10, v11);
            }
        }
    }
}

// ---------------- SGEMM small (32x32, 64 threads) for GEMM3 ----------------
template <int BM, int TM>
__global__ __launch_bounds__(64) void sgemm_relu(const float* __restrict__ A,
                                                 const float* __restrict__ B,
                                                 const float* __restrict__ bias,
                                                 float* __restrict__ C,
                                                 int M, int N, int K) {
    constexpr int BK = 8;
    constexpr int LPT = (BM * BK / 4) / 64;
    const int tid = threadIdx.x;
    const int tx = tid & 7;
    const int ty = tid >> 3;
    const int m0 = blockIdx.y * BM;
    const int n0 = blockIdx.x * BM;
    __shared__ float As[BK][BM];
    __shared__ float Bs[BK][BM];
    float acc[TM][TM];
#pragma unroll
    for (int i = 0; i < TM; i++)
#pragma unroll
        for (int j = 0; j < TM; j++) acc[i][j] = 0.f;

    float4 pa[LPT], pb[LPT];
    const int nt = K / BK;

    auto loadG = [&](int t) {
        int k0 = t * BK;
#pragma unroll
        for (int L = 0; L < LPT; L++) {
            int i = tid + L * 64;
            int ar = i >> 1, ag = i & 1;
            pa[L] = *(const float4*)(A + (size_t)(m0 + ar) * K + k0 + ag * 4);
            int bk = i / (BM / 4), bc = i % (BM / 4);
            pb[L] = *(const float4*)(B + (size_t)(k0 + bk) * N + n0 + bc * 4);
        }
    };
    auto storeS = [&]() {
#pragma unroll
        for (int L = 0; L < LPT; L++) {
            int i = tid + L * 64;
            int ar = i >> 1, ag = i & 1;
            As[ag * 4 + 0][ar] = pa[L].x; As[ag * 4 + 1][ar] = pa[L].y;
            As[ag * 4 + 2][ar] = pa[L].z; As[ag * 4 + 3][ar] = pa[L].w;
            int bk = i / (BM / 4), bc = i % (BM / 4);
            *(float4*)(&Bs[bk][bc * 4]) = pb[L];
        }
    };

    loadG(0); storeS(); __syncthreads();
    for (int t = 0; t < nt; t++) {
        if (t + 1 < nt) loadG(t + 1);
#pragma unroll
        for (int kk = 0; kk < BK; kk++) {
            float af[TM], bf[TM];
#pragma unroll
            for (int i = 0; i < TM; i += 4) {
                float4 qa = *(const float4*)(&As[kk][ty * TM + i]);
                af[i] = qa.x; af[i + 1] = qa.y; af[i + 2] = qa.z; af[i + 3] = qa.w;
            }
#pragma unroll
            for (int j = 0; j < TM; j += 4) {
                float4 qb = *(const float4*)(&Bs[kk][tx * TM + j]);
                bf[j] = qb.x; bf[j + 1] = qb.y; bf[j + 2] = qb.z; bf[j + 3] = qb.w;
            }
#pragma unroll
            for (int i = 0; i < TM; i++)
#pragma unroll
                for (int j = 0; j < TM; j++) acc[i][j] = fmaf(af[i], bf[j], acc[i][j]);
        }
        __syncthreads();
        if (t + 1 < nt) { storeS(); __syncthreads(); }
    }
#pragma unroll
    for (int i = 0; i < TM; i++) {
        int m = m0 + ty * TM + i;
#pragma unroll
        for (int j = 0; j < TM; j += 4) {
            int n = n0 + tx * TM + j;
            float4 o;
            o.x = fmaxf(acc[i][j] + bias[n], 0.f);
            o.y = fmaxf(acc[i][j + 1] + bias[n + 1], 0.f);
            o.z = fmaxf(acc[i][j + 2] + bias[n + 2], 0.f);
            o.w = fmaxf(acc[i][j + 3] + bias[n + 3], 0.f);
            *(float4*)(C + (size_t)m * N + n) = o;
        }
    }
}

// ---------------- last tiny FC ----------------
__global__ void k_fc4(const float* __restrict__ w4, const float* __restrict__ b4,
                      float* __restrict__ out) {
    int idx = blockIdx.x * blockDim.x + threadIdx.x;
    if (idx >= BATCH * 10) return;
    int b = idx / 10, n = idx - b * 10;
    const float* a = g_a3 + b * 128;
    float acc = b4[n];
#pragma unroll 8
    for (int k = 0; k < 128; k++) acc = fmaf(a[k], w4[k * 10 + n], acc);
    out[idx] = fmaxf(acc, 0.f);
}

// ---------------- launch ----------------
extern "C" void kernel_launch(void* const* d_in, const int* in_sizes, int n_in,
                              void* d_out, int out_size) {
    const float* x       = (const float*)d_in[0];
    const float* la_a    = (const float*)d_in[1];
    const float* la_b    = (const float*)d_in[2];
    const float* la_bias = (const float*)d_in[3];
    const float* bn1_g   = (const float*)d_in[4];
    const float* bn1_b   = (const float*)d_in[5];
    const float* a1_w    = (const float*)d_in[6];
    const float* a1_b    = (const float*)d_in[7];
    const float* e1_w    = (const float*)d_in[8];
    const float* e1_b    = (const float*)d_in[9];
    const float* bn2_g   = (const float*)d_in[10];
    const float* bn2_b   = (const float*)d_in[11];
    const float* e2_w    = (const float*)d_in[12];
    const float* e2_b    = (const float*)d_in[13];
    const float* f1_w    = (const float*)d_in[14];
    const float* f1_b    = (const float*)d_in[15];
    const float* fa_w    = (const float*)d_in[16];
    const float* fa_b    = (const float*)d_in[17];
    const float* bn3_g   = (const float*)d_in[18];
    const float* bn3_b   = (const float*)d_in[19];
    const float* f2_w    = (const float*)d_in[20];
    const float* f2_b    = (const float*)d_in[21];
    const float* w1 = (const float*)d_in[22]; const float* b1 = (const float*)d_in[23];
    const float* w2 = (const float*)d_in[24]; const float* b2 = (const float*)d_in[25];
    const float* w3 = (const float*)d_in[26]; const float* b3 = (const float*)d_in[27];
    const float* w4 = (const float*)d_in[28]; const float* b4 = (const float*)d_in[29];
    float* out = (float*)d_out;

    float *p_a2 = nullptr, *p_a3 = nullptr;
    __nv_bfloat16 *p_zhi, *p_zlo, *p_w1hi, *p_w1lo, *p_a1hi, *p_a1lo, *p_w2hi, *p_w2lo;
    cudaGetSymbolAddress((void**)&p_a2, g_a2);
    cudaGetSymbolAddress((void**)&p_a3, g_a3);
    cudaGetSymbolAddress((void**)&p_zhi, g_zhi);
    cudaGetSymbolAddress((void**)&p_zlo, g_zlo);
    cudaGetSymbolAddress((void**)&p_w1hi, g_w1hi);
    cudaGetSymbolAddress((void**)&p_w1lo, g_w1lo);
    cudaGetSymbolAddress((void**)&p_a1hi, g_a1hi);
    cudaGetSymbolAddress((void**)&p_a1lo, g_a1lo);
    cudaGetSymbolAddress((void**)&p_w2hi, g_w2hi);
    cudaGetSymbolAddress((void**)&p_w2lo, g_w2lo);

    k_xstats<<<BATCH, 256>>>(x, la_a, la_b);
    k_redbn1<<<1, 544>>>(la_bias, bn1_g, bn1_b);
    k_wsplit<<<dim3(1024 / 32, 768 / 32), 256>>>(w1, p_w1hi, p_w1lo, 768, 1024);
    k_wsplit<<<dim3(512 / 32, 1024 / 32), 256>>>(w2, p_w2hi, p_w2lo, 1024, 512);
    k_branch<<<BATCH, 256>>>(x, la_bias, a1_w, a1_b, e1_w, e1_b,
                             f1_w, f1_b, fa_w, fa_b);
    k_bn23<<<dim3(CH, 2), 256>>>(bn2_g, bn2_b, bn3_g, bn3_b);
    k_final<<<BATCH, 128>>>(e2_w, e2_b, f2_w, f2_b);
    // GEMM1: (1024x1024x768) split-bf16 HMMA, emits a1 hi/lo
    hgemm_split<1><<<dim3(1024 / 64, 1024 / 128), 256>>>(
        p_zhi, p_zlo, p_w1hi, p_w1lo, b1, nullptr, p_a1hi, p_a1lo, 1024, 1024, 768);
    // GEMM2: (1024x512x1024) split-bf16 HMMA, emits a2 fp32
    hgemm_split<0><<<dim3(512 / 64, 1024 / 128), 256>>>(
        p_a1hi, p_a1lo, p_w2hi, p_w2lo, b2, p_a2, nullptr, nullptr, 1024, 512, 1024);
    sgemm_relu<32, 4><<<dim3(128 / 32, 1024 / 32), 64>>>(p_a2, w3, b3, p_a3, 1024, 128, 512);
    k_fc4<<<(BATCH * 10 + 127) / 128, 128>>>(w4, b4, out);
}

// round 17
// speedup vs baseline: 1.2847x; 1.0104x over previous
#include <cuda_runtime.h>
#include <cuda_bf16.h>
#include <math.h>

#define BATCH 1024
#define CH 32
#define LIN 1024
#define LCONV 1041
#define LH 520

typedef unsigned int u32;

// ---------------- scratch (device globals; no allocation) ----------------
__device__ float g_filt[CH * 16];
__device__ float g_xpart[BATCH * 17];
__device__ float g_bn1_sc3[CH];
__device__ float g_bn1_sh[CH];
__device__ float g_x1pre[BATCH * CH * 31];
__device__ float g_x2pre[BATCH * CH * 31];
__device__ float g_p2s[CH * BATCH];
__device__ float g_p2q[CH * BATCH];
__device__ float g_p3s[CH * BATCH];
__device__ float g_p3q[CH * BATCH];
__device__ float g_bn2_sc[CH], g_bn2_sh[CH], g_bn3_sc[CH], g_bn3_sh[CH];
// split-bf16 buffers
__device__ __align__(16) __nv_bfloat16 g_zhi[BATCH * 768];
__device__ __align__(16) __nv_bfloat16 g_zlo[BATCH * 768];
__device__ __align__(16) __nv_bfloat16 g_w1hi[1024 * 768];   // [N][K] transposed
__device__ __align__(16) __nv_bfloat16 g_w1lo[1024 * 768];
__device__ __align__(16) __nv_bfloat16 g_a1hi[BATCH * 1024];
__device__ __align__(16) __nv_bfloat16 g_a1lo[BATCH * 1024];
__device__ __align__(16) __nv_bfloat16 g_w2hi[512 * 1024];   // [N][K] transposed
__device__ __align__(16) __nv_bfloat16 g_w2lo[512 * 1024];
__device__ __align__(16) __nv_bfloat16 g_a2hi[BATCH * 512];
__device__ __align__(16) __nv_bfloat16 g_a2lo[BATCH * 512];
__device__ __align__(16) __nv_bfloat16 g_w3hi[128 * 512];    // [N][K] transposed
__device__ __align__(16) __nv_bfloat16 g_w3lo[128 * 512];
__device__ float g_a3[BATCH * 128];

// ---------------- x row statistics (+ filter bank computed by block 0) ----------------
// Register-window inner loop: 5 LDS.128 per thread, all FMAs from registers.
__global__ __launch_bounds__(256) void k_xstats(const float* __restrict__ x,
                                                const float* __restrict__ la_a,
                                                const float* __restrict__ la_b) {
    __shared__ __align__(16) float xs[LIN + 16];
    __shared__ float part[8][17];
    int b = blockIdx.x, tid = threadIdx.x;
    int warp = tid >> 5, lane = tid & 31;

    if (b == 0) {
        for (int idx = tid; idx < CH * 16; idx += 256) {
            int c = idx >> 4, k = idx & 15;
            const double A = 0.08, ep = 0.03, tal = 0.1;
            const double w = 6.283185307179586 * 50.0;
            const double coef = -ep / sqrt(1.0 - ep * ep);
            double ratio = (double)la_b[c] / (double)la_a[c];
            double t = (double)k / 15.0;
            double arg = w * (t - ratio - tal);
            g_filt[c * 16 + k] = (float)(A * exp(coef * arg) * (-sin(arg)));
        }
    }

    for (int i = tid; i < LIN + 16; i += 256)
        xs[i] = (i < LIN) ? x[b * LIN + i] : 0.f;
    __syncthreads();
    float r[20];
    {
        const float4* p4 = (const float4*)&xs[4 * tid];
#pragma unroll
        for (int w = 0; w < 5; w++) {
            float4 q = p4[w];
            r[4 * w] = q.x; r[4 * w + 1] = q.y; r[4 * w + 2] = q.z; r[4 * w + 3] = q.w;
        }
    }
    float acc[16];
#pragma unroll
    for (int d = 0; d < 16; d++) acc[d] = 0.f;
    float s = 0.f;
#pragma unroll
    for (int j = 0; j < 4; j++) {
        float xi = r[j];
        s += xi;
#pragma unroll
        for (int d = 0; d < 16; d++) acc[d] = fmaf(xi, r[j + d], acc[d]);
    }
#pragma unroll
    for (int off = 16; off > 0; off >>= 1) {
        s += __shfl_down_sync(0xffffffffu, s, off);
#pragma unroll
        for (int d = 0; d < 16; d++)
            acc[d] += __shfl_down_sync(0xffffffffu, acc[d], off);
    }
    if (lane == 0) {
#pragma unroll
        for (int d = 0; d < 16; d++) part[warp][d] = acc[d];
        part[warp][16] = s;
    }
    __syncthreads();
    if (tid < 17) {
        float t = 0.f;
#pragma unroll
        for (int w = 0; w < 8; w++) t += part[w][tid];
        g_xpart[b * 17 + tid] = t;
    }
}

// ---------------- fused reduction + BN1 affine ----------------
__global__ __launch_bounds__(544) void k_redbn1(const float* __restrict__ la_bias,
                                                const float* __restrict__ g1,
                                                const float* __restrict__ b1) {
    __shared__ double Rs[17];
    int tid = threadIdx.x, warp = tid >> 5, lane = tid & 31;
    if (warp < 17) {
        double s = 0;
        for (int b = lane; b < BATCH; b += 32) s += (double)g_xpart[b * 17 + warp];
#pragma unroll
        for (int off = 16; off > 0; off >>= 1)
            s += __shfl_down_sync(0xffffffffu, s, off);
        if (lane == 0) Rs[warp] = s;
    }
    __syncthreads();
    if (tid < CH * 16) {
        int c = tid >> 4, k = tid & 15;
        double fk = (double)g_filt[c * 16 + k];
        double q = 0;
#pragma unroll
        for (int k2 = 0; k2 < 16; k2++) {
            int d = k2 - k; if (d < 0) d = -d;
            q += (double)g_filt[c * 16 + k2] * Rs[d];
        }
        q *= fk;
        double F1p = fk;
#pragma unroll
        for (int off = 8; off > 0; off >>= 1) {
            q += __shfl_down_sync(0xffffffffu, q, off, 16);
            F1p += __shfl_down_sync(0xffffffffu, F1p, off, 16);
        }
        if (k == 0) {
            double S = Rs[16];
            double N = (double)BATCH * (double)LCONV;
            double Ey = F1p * S / N;
            double var = q / N - Ey * Ey;
            double mean = (double)la_bias[c] + Ey;
            double inv = 1.0 / sqrt(var + 1e-5);
            double sc = (double)g1[c] * inv;
            g_bn1_sc3[c] = (float)(sc / 3.0);
            g_bn1_sh[c] = (float)((double)b1[c] - mean * sc);
        }
    }
}

// ---------------- pass 2: fused conv+BN+avgpool -> register-resident branches ----------------
#define HPAD 556
__global__ __launch_bounds__(256) void k_branch(
    const float* __restrict__ x, const float* __restrict__ la_bias,
    const float* __restrict__ a1_w, const float* __restrict__ a1_b,
    const float* __restrict__ e1_w, const float* __restrict__ e1_b,
    const float* __restrict__ f1_w, const float* __restrict__ f1_b,
    const float* __restrict__ fa_w, const float* __restrict__ fa_b) {
    __shared__ __align__(16) float xsg[130 * 28];
    __shared__ float hw[8][HPAD];
    int b = blockIdx.x, tid = threadIdx.x;
    int warp = tid >> 5, lane = tid & 31;
    const float* xr = x + b * LIN;

    for (int idx = tid; idx < 130 * 24; idx += 256) {
        int g = idx / 24, j = idx - g * 24;
        int pos = 8 * g + j;
        xsg[g * 28 + j] = (pos >= 16 && pos < 16 + LIN) ? xr[pos - 16] : 0.f;
    }
    __syncthreads();

    float* h = hw[warp];

    for (int cg = 0; cg < 4; cg++) {
        int c = warp + 8 * cg;
        float fw[16];
#pragma unroll
        for (int k = 0; k < 16; k++) fw[k] = g_filt[c * 16 + k];
        float cw[18];
#pragma unroll
        for (int j = 0; j < 18; j++) {
            float s = 0.f;
#pragma unroll
            for (int p = 0; p < 3; p++) {
                int k = j - p;
                if (k >= 0 && k < 16) s += fw[k];
            }
            cw[j] = s;
        }
        float sc3 = g_bn1_sc3[c];
        float sh2 = fmaf(3.f * la_bias[c], sc3, g_bn1_sh[c]);

        for (int g = lane; g < 130; g += 32) {
            const float4* p4 = (const float4*)&xsg[g * 28];
            float r[24];
#pragma unroll
            for (int w = 0; w < 6; w++) {
                float4 q = p4[w];
                r[4 * w] = q.x; r[4 * w + 1] = q.y; r[4 * w + 2] = q.z; r[4 * w + 3] = q.w;
            }
            int base = 4 * g + (g >> 2);
#pragma unroll
            for (int d = 0; d < 4; d++) {
                float s = 0.f;
#pragma unroll
                for (int j = 0; j < 18; j++) s = fmaf(r[2 * d + j], cw[j], s);
                h[base + d] = fmaf(s, sc3, sh2);
            }
        }
        __syncwarp();

        float mvA = 0.f, mvB = 0.f;
        if (lane < 31) {
            int hb = 17 * lane;
            float hr[34];
#pragma unroll
            for (int j = 0; j < 34; j++) hr[j] = h[hb + j + (j >> 4)];

            {
                float w8[8];
#pragma unroll
                for (int k = 0; k < 8; k++) w8[k] = a1_w[c * 8 + k];
                float wsum = 0.f;
#pragma unroll
                for (int k = 0; k < 8; k++) wsum += w8[k];
                float wbA = a1_b[c] - wsum;
                float ua[14];
#pragma unroll
                for (int i = 0; i < 14; i++) {
                    float a = wbA;
#pragma unroll
                    for (int k = 0; k < 8; k++) a = fmaf(hr[2 * i + k], w8[k], a);
                    ua[i] = fmaxf(a, 0.f);
                }
                float wE[8];
#pragma unroll
                for (int k = 0; k < 8; k++) wE[k] = e1_w[c * 8 + k];
                float wbE = 1.f - e1_b[c];
#pragma unroll
                for (int j = 0; j < 4; j++) {
                    float a = wbE;
#pragma unroll
                    for (int k = 0; k < 8; k++) a = fmaf(ua[2 * j + k], wE[k], a);
                    mvA = fmaxf(mvA, a);
                }
                g_x1pre[(b * CH + c) * 31 + lane] = mvA;
            }
            {
                float w8[8];
#pragma unroll
                for (int k = 0; k < 8; k++) w8[k] = f1_w[c * 8 + k];
                float wbF = 1.f - f1_b[c];
                float ub[14];
#pragma unroll
                for (int i = 0; i < 14; i++) {
                    float a = wbF;
#pragma unroll
                    for (int k = 0; k < 8; k++) a = fmaf(hr[2 * i + k], w8[k], a);
                    ub[i] = fmaxf(a, 0.f);
                }
                float wA[8];
#pragma unroll
                for (int k = 0; k < 8; k++) wA[k] = fa_w[c * 8 + k];
                float wsum = 0.f;
#pragma unroll
                for (int k = 0; k < 8; k++) wsum += wA[k];
                float wbA2 = fa_b[c] - wsum;
#pragma unroll
                for (int j = 0; j < 4; j++) {
                    float a = wbA2;
#pragma unroll
                    for (int k = 0; k < 8; k++) a = fmaf(ub[2 * j + k], wA[k], a);
                    mvB = fmaxf(mvB, a);
                }
                g_x2pre[(b * CH + c) * 31 + lane] = mvB;
            }
        }
        float sA = mvA, qA = mvA * mvA, sB = mvB, qB = mvB * mvB;
#pragma unroll
        for (int off = 16; off > 0; off >>= 1) {
            sA += __shfl_down_sync(0xffffffffu, sA, off);
            qA += __shfl_down_sync(0xffffffffu, qA, off);
            sB += __shfl_down_sync(0xffffffffu, sB, off);
            qB += __shfl_down_sync(0xffffffffu, qB, off);
        }
        if (lane == 0) {
            g_p2s[c * BATCH + b] = sA; g_p2q[c * BATCH + b] = qA;
            g_p3s[c * BATCH + b] = sB; g_p3q[c * BATCH + b] = qB;
        }
        __syncwarp();
    }
}

// ---------------- finalize BN2 / BN3 affine (coalesced) ----------------
__global__ __launch_bounds__(256) void k_bn23(const float* __restrict__ g2,
                                              const float* __restrict__ b2,
                                              const float* __restrict__ g3,
                                              const float* __restrict__ b3) {
    int c = blockIdx.x, which = blockIdx.y, tid = threadIdx.x;
    int warp = tid >> 5, lane = tid & 31;
    const float* ps = (which ? g_p3s : g_p2s) + c * BATCH;
    const float* pq = (which ? g_p3q : g_p2q) + c * BATCH;
    double s = 0, q = 0;
    for (int b = tid; b < BATCH; b += 256) {
        s += (double)ps[b];
        q += (double)pq[b];
    }
#pragma unroll
    for (int off = 16; off > 0; off >>= 1) {
        s += __shfl_down_sync(0xffffffffu, s, off);
        q += __shfl_down_sync(0xffffffffu, q, off);
    }
    __shared__ double ss[8], sq[8];
    if (lane == 0) { ss[warp] = s; sq[warp] = q; }
    __syncthreads();
    if (tid == 0) {
        double S = 0, Q = 0;
#pragma unroll
        for (int w = 0; w < 8; w++) { S += ss[w]; Q += sq[w]; }
        double N = (double)BATCH * 31.0;
        double mean = S / N;
        double var = Q / N - mean * mean;
        double inv = 1.0 / sqrt(var + 1e-5);
        double gg = which ? (double)g3[c] : (double)g2[c];
        double bb = which ? (double)b3[c] : (double)b2[c];
        double sc = gg * inv;
        if (which) { g_bn3_sc[c] = (float)sc; g_bn3_sh[c] = (float)(bb - mean * sc); }
        else       { g_bn2_sc[c] = (float)sc; g_bn2_sh[c] = (float)(bb - mean * sc); }
    }
}

// ---------------- BN + final conv -> z features emitted as split bf16 ----------------
__global__ __launch_bounds__(128) void k_final(const float* __restrict__ e2_w,
                                               const float* __restrict__ e2_b,
                                               const float* __restrict__ f2_w,
                                               const float* __restrict__ f2_b) {
    int b = blockIdx.x;
    for (int idx = threadIdx.x; idx < 768; idx += 128) {
        int ct = idx / 12, j = idx % 12;
        int c = ct & 31;
        bool second = ct >= 32;
        const float* pre = (second ? g_x2pre : g_x1pre) + (b * CH + c) * 31 + 2 * j;
        const float* w = (second ? f2_w : e2_w) + c * 8;
        float base = 1.f - (second ? f2_b[c] : e2_b[c]);
        float sc = second ? g_bn3_sc[c] : g_bn2_sc[c];
        float shv = second ? g_bn3_sh[c] : g_bn2_sh[c];
        float sw = 0.f, dot = 0.f;
#pragma unroll
        for (int k = 0; k < 8; k++) { sw += w[k]; dot = fmaf(pre[k], w[k], dot); }
        float val = fmaxf(base + shv * sw + sc * dot, 0.f);
        __nv_bfloat16 hi = __float2bfloat16(val);
        __nv_bfloat16 lo = __float2bfloat16(val - __bfloat162float(hi));
        g_zhi[b * 768 + idx] = hi;
        g_zlo[b * 768 + idx] = lo;
    }
}

// ---------------- weight transpose + split: w[K][N] fp32 -> wt_hi/lo[N][K] bf16 ----------------
__global__ __launch_bounds__(256) void k_wsplit(const float* __restrict__ w,
                                                __nv_bfloat16* __restrict__ whi,
                                                __nv_bfloat16* __restrict__ wlo,
                                                int K, int N) {
    __shared__ float ts[32][33];
    int n0 = blockIdx.x * 32, k0 = blockIdx.y * 32;
    int tx = threadIdx.x & 31, ty = threadIdx.x >> 5;
#pragma unroll
    for (int i = 0; i < 4; i++)
        ts[ty + i * 8][tx] = w[(size_t)(k0 + ty + i * 8) * N + n0 + tx];
    __syncthreads();
#pragma unroll
    for (int i = 0; i < 4; i++) {
        float v = ts[tx][ty + i * 8];
        __nv_bfloat16 hi = __float2bfloat16(v);
        __nv_bfloat16 lo = __float2bfloat16(v - __bfloat162float(hi));
        size_t o = (size_t)(n0 + ty + i * 8) * K + k0 + tx;
        whi[o] = hi; wlo[o] = lo;
    }
}

// ---------------- split-bf16 HMMA GEMM: C = relu(A@B^T + bias) ----------------
__device__ __forceinline__ void mma_bf16(float* d, const u32* a, const u32* b) {
    asm volatile(
        "mma.sync.aligned.m16n8k16.row.col.f32.bf16.bf16.f32 "
        "{%0,%1,%2,%3}, {%4,%5,%6,%7}, {%8,%9}, {%0,%1,%2,%3};\n"
        : "+f"(d[0]), "+f"(d[1]), "+f"(d[2]), "+f"(d[3])
        : "r"(a[0]), "r"(a[1]), "r"(a[2]), "r"(a[3]), "r"(b[0]), "r"(b[1]));
}

template <int EMIT_SPLIT>
__global__ __launch_bounds__(256) void hgemm_split(
    const __nv_bfloat16* __restrict__ Ahi, const __nv_bfloat16* __restrict__ Alo,
    const __nv_bfloat16* __restrict__ Bhi, const __nv_bfloat16* __restrict__ Blo,
    const float* __restrict__ bias,
    float* __restrict__ Cf,
    __nv_bfloat16* __restrict__ Chi, __nv_bfloat16* __restrict__ Clo,
    int M, int N, int K) {
    constexpr int BM = 128, BN = 64, BK = 32;
    __shared__ u32 AsH[128 * 20], AsL[128 * 20], BsH[64 * 20], BsL[64 * 20];
    const int tid = threadIdx.x;
    const int warp = tid >> 5, lane = tid & 31;
    const int g = lane >> 2, tg = lane & 3;
    const int wm = (warp & 3) * 32, wn = (warp >> 2) * 32;
    const int m0 = blockIdx.y * BM, n0 = blockIdx.x * BN;

    float acc[2][4][4];
#pragma unroll
    for (int f = 0; f < 2; f++)
#pragma unroll
        for (int j = 0; j < 4; j++)
#pragma unroll
            for (int e = 0; e < 4; e++) acc[f][j][e] = 0.f;

    const int ra = tid >> 1, pa = tid & 1;
    const int rb = tid >> 2, qb = tid & 3;
    const int nt = K / BK;

    for (int t = 0; t < nt; t++) {
        int k0 = t * BK;
        __syncthreads();
        {
            const uint4* gah = (const uint4*)(Ahi + (size_t)(m0 + ra) * K + k0);
            const uint4* gal = (const uint4*)(Alo + (size_t)(m0 + ra) * K + k0);
            uint4* sh = (uint4*)&AsH[ra * 20 + pa * 8];
            uint4* sl = (uint4*)&AsL[ra * 20 + pa * 8];
            sh[0] = gah[2 * pa]; sh[1] = gah[2 * pa + 1];
            sl[0] = gal[2 * pa]; sl[1] = gal[2 * pa + 1];
            ((uint4*)&BsH[rb * 20 + qb * 4])[0] =
                ((const uint4*)(Bhi + (size_t)(n0 + rb) * K + k0))[qb];
            ((uint4*)&BsL[rb * 20 + qb * 4])[0] =
                ((const uint4*)(Blo + (size_t)(n0 + rb) * K + k0))[qb];
        }
        __syncthreads();
#pragma unroll
        for (int ks = 0; ks < 2; ks++) {
            int ko = ks * 8;
            u32 ah[2][4], al[2][4];
#pragma unroll
            for (int f = 0; f < 2; f++) {
                int r0 = wm + f * 16 + g;
                ah[f][0] = AsH[r0 * 20 + ko + tg];
                ah[f][1] = AsH[(r0 + 8) * 20 + ko + tg];
                ah[f][2] = AsH[r0 * 20 + ko + tg + 4];
                ah[f][3] = AsH[(r0 + 8) * 20 + ko + tg + 4];
                al[f][0] = AsL[r0 * 20 + ko + tg];
                al[f][1] = AsL[(r0 + 8) * 20 + ko + tg];
                al[f][2] = AsL[r0 * 20 + ko + tg + 4];
                al[f][3] = AsL[(r0 + 8) * 20 + ko + tg + 4];
            }
            u32 bh[4][2], bl[4][2];
#pragma unroll
            for (int j = 0; j < 4; j++) {
                int rn = wn + j * 8 + g;
                bh[j][0] = BsH[rn * 20 + ko + tg];
                bh[j][1] = BsH[rn * 20 + ko + tg + 4];
                bl[j][0] = BsL[rn * 20 + ko + tg];
                bl[j][1] = BsL[rn * 20 + ko + tg + 4];
            }
#pragma unroll
            for (int f = 0; f < 2; f++)
#pragma unroll
                for (int j = 0; j < 4; j++) {
                    mma_bf16(acc[f][j], ah[f], bh[j]);
                    mma_bf16(acc[f][j], ah[f], bl[j]);
                    mma_bf16(acc[f][j], al[f], bh[j]);
                }
        }
    }
#pragma unroll
    for (int f = 0; f < 2; f++) {
        int row = m0 + wm + f * 16 + g;
#pragma unroll
        for (int j = 0; j < 4; j++) {
            int col = n0 + wn + j * 8 + tg * 2;
            float bv0 = bias[col], bv1 = bias[col + 1];
            float v00 = fmaxf(acc[f][j][0] + bv0, 0.f);
            float v01 = fmaxf(acc[f][j][1] + bv1, 0.f);
            float v10 = fmaxf(acc[f][j][2] + bv0, 0.f);
            float v11 = fmaxf(acc[f][j][3] + bv1, 0.f);
            if (EMIT_SPLIT) {
                __nv_bfloat162 h0, l0, h1, l1;
                h0.x = __float2bfloat16(v00);
                h0.y = __float2bfloat16(v01);
                l0.x = __float2bfloat16(v00 - __bfloat162float(h0.x));
                l0.y = __float2bfloat16(v01 - __bfloat162float(h0.y));
                h1.x = __float2bfloat16(v10);
                h1.y = __float2bfloat16(v11);
                l1.x = __float2bfloat16(v10 - __bfloat162float(h1.x));
                l1.y = __float2bfloat16(v11 - __bfloat162float(h1.y));
                *(__nv_bfloat162*)(Chi + (size_t)row * N + col) = h0;
                *(__nv_bfloat162*)(Clo + (size_t)row * N + col) = l0;
                *(__nv_bfloat162*)(Chi + (size_t)(row + 8) * N + col) = h1;
                *(__nv_bfloat162*)(Clo + (size_t)(row + 8) * N + col) = l1;
            } else {
                *(float2*)(Cf + (size_t)row * N + col) = make_float2(v00, v01);
                *(float2*)(Cf + (size_t)(row + 8) * N + col) = make_float2(v10, v11);
            }
        }
    }
}

// ---------------- last tiny FC ----------------
__global__ void k_fc4(const float* __restrict__ w4, const float* __restrict__ b4,
                      float* __restrict__ out) {
    int idx = blockIdx.x * blockDim.x + threadIdx.x;
    if (idx >= BATCH * 10) return;
    int b = idx / 10, n = idx - b * 10;
    const float* a = g_a3 + b * 128;
    float acc = b4[n];
#pragma unroll 8
    for (int k = 0; k < 128; k++) acc = fmaf(a[k], w4[k * 10 + n], acc);
    out[idx] = fmaxf(acc, 0.f);
}

// ---------------- launch ----------------
extern "C" void kernel_launch(void* const* d_in, const int* in_sizes, int n_in,
                              void* d_out, int out_size) {
    const float* x       = (const float*)d_in[0];
    const float* la_a    = (const float*)d_in[1];
    const float* la_b    = (const float*)d_in[2];
    const float* la_bias = (const float*)d_in[3];
    const float* bn1_g   = (const float*)d_in[4];
    const float* bn1_b   = (const float*)d_in[5];
    const float* a1_w    = (const float*)d_in[6];
    const float* a1_b    = (const float*)d_in[7];
    const float* e1_w    = (const float*)d_in[8];
    const float* e1_b    = (const float*)d_in[9];
    const float* bn2_g   = (const float*)d_in[10];
    const float* bn2_b   = (const float*)d_in[11];
    const float* e2_w    = (const float*)d_in[12];
    const float* e2_b    = (const float*)d_in[13];
    const float* f1_w    = (const float*)d_in[14];
    const float* f1_b    = (const float*)d_in[15];
    const float* fa_w    = (const float*)d_in[16];
    const float* fa_b    = (const float*)d_in[17];
    const float* bn3_g   = (const float*)d_in[18];
    const float* bn3_b   = (const float*)d_in[19];
    const float* f2_w    = (const float*)d_in[20];
    const float* f2_b    = (const float*)d_in[21];
    const float* w1 = (const float*)d_in[22]; const float* b1 = (const float*)d_in[23];
    const float* w2 = (const float*)d_in[24]; const float* b2 = (const float*)d_in[25];
    const float* w3 = (const float*)d_in[26]; const float* b3 = (const float*)d_in[27];
    const float* w4 = (const float*)d_in[28]; const float* b4 = (const float*)d_in[29];
    float* out = (float*)d_out;

    float* p_a3 = nullptr;
    __nv_bfloat16 *p_zhi, *p_zlo, *p_w1hi, *p_w1lo, *p_a1hi, *p_a1lo;
    __nv_bfloat16 *p_w2hi, *p_w2lo, *p_a2hi, *p_a2lo, *p_w3hi, *p_w3lo;
    cudaGetSymbolAddress((void**)&p_a3, g_a3);
    cudaGetSymbolAddress((void**)&p_zhi, g_zhi);
    cudaGetSymbolAddress((void**)&p_zlo, g_zlo);
    cudaGetSymbolAddress((void**)&p_w1hi, g_w1hi);
    cudaGetSymbolAddress((void**)&p_w1lo, g_w1lo);
    cudaGetSymbolAddress((void**)&p_a1hi, g_a1hi);
    cudaGetSymbolAddress((void**)&p_a1lo, g_a1lo);
    cudaGetSymbolAddress((void**)&p_w2hi, g_w2hi);
    cudaGetSymbolAddress((void**)&p_w2lo, g_w2lo);
    cudaGetSymbolAddress((void**)&p_a2hi, g_a2hi);
    cudaGetSymbolAddress((void**)&p_a2lo, g_a2lo);
    cudaGetSymbolAddress((void**)&p_w3hi, g_w3hi);
    cudaGetSymbolAddress((void**)&p_w3lo, g_w3lo);

    k_xstats<<<BATCH, 256>>>(x, la_a, la_b);
    k_redbn1<<<1, 544>>>(la_bias, bn1_g, bn1_b);
    k_wsplit<<<dim3(1024 / 32, 768 / 32), 256>>>(w1, p_w1hi, p_w1lo, 768, 1024);
    k_wsplit<<<dim3(512 / 32, 1024 / 32), 256>>>(w2, p_w2hi, p_w2lo, 1024, 512);
    k_wsplit<<<dim3(128 / 32, 512 / 32), 256>>>(w3, p_w3hi, p_w3lo, 512, 128);
    k_branch<<<BATCH, 256>>>(x, la_bias, a1_w, a1_b, e1_w, e1_b,
                             f1_w, f1_b, fa_w, fa_b);
    k_bn23<<<dim3(CH, 2), 256>>>(bn2_g, bn2_b, bn3_g, bn3_b);
    k_final<<<BATCH, 128>>>(e2_w, e2_b, f2_w, f2_b);
    // GEMM1: (1024x1024x768) split-bf16 HMMA, emits a1 hi/lo
    hgemm_split<1><<<dim3(1024 / 64, 1024 / 128), 256>>>(
        p_zhi, p_zlo, p_w1hi, p_w1lo, b1, nullptr, p_a1hi, p_a1lo, 1024, 1024, 768);
    // GEMM2: (1024x512x1024) split-bf16 HMMA, emits a2 hi/lo
    hgemm_split<1><<<dim3(512 / 64, 1024 / 128), 256>>>(
        p_a1hi, p_a1lo, p_w2hi, p_w2lo, b2, nullptr, p_a2hi, p_a2lo, 1024, 512, 1024);
    // GEMM3: (1024x128x512) split-bf16 HMMA, emits a3 fp32
    hgemm_split<0><<<dim3(128 / 64, 1024 / 128), 256>>>(
        p_a2hi, p_a2lo, p_w3hi, p_w3lo, b3, p_a3, nullptr, nullptr, 1024, 128, 512);
    k_fc4<<<(BATCH * 10 + 127) / 128, 128>>>(w4, b4, out);
}